// round 4
// baseline (speedup 1.0000x reference)
#include <cuda_runtime.h>

// Problem: B=2, M=2048, HID=1024, NH=16, D=64
//   final = ((h Wq^T)(h Wk^T)^T (h Wv^T)) Wo^T   per head, concatenated.
// No softmax => use associativity:
//   S_bh   = K_bh^T V_bh                      (64x64 per (b,h))
//   U_b[:, hD:hD+D] = Wq_h^T S_bh             (1024x1024 per batch)
//   C_b    = U_b Wo^T                         (1024x1024 per batch)
//   final_b = h_b C_b                         (2048x1024 per batch)
// Avoids the 1 GB attention matrix entirely; total ~30 GFLOP fp32.

#define HIDD   1024
#define MSEQ   2048
#define NBATCH 2
#define NHEAD  16
#define DHEAD  64
#define SPLITS 8

// Scratch (device globals; no allocation allowed in kernel_launch)
__device__ float g_K[NBATCH * MSEQ * HIDD];                       // 16 MB
__device__ float g_V[NBATCH * MSEQ * HIDD];                       // 16 MB
__device__ float g_Spart[SPLITS * NBATCH * NHEAD * DHEAD * DHEAD];// 4 MB
__device__ float g_U[NBATCH * HIDD * HIDD];                       // 8 MB
__device__ float g_C[NBATCH * HIDD * HIDD];                       // 8 MB

// ---------------------------------------------------------------------------
// SGEMM: C[M,N] = A[M,K] * op(B), row-major.
//   TB=true : op(B) = B^T with B stored [N,K]  (C[i,j] = sum_k A[i,k]*B[j,k])
//   TB=false: op(B) = B   with B stored [K,N]
// BM=BN=128, BK=16, 256 threads, 8x8 microtile. M,N multiples of 128,
// K multiple of 16 (all true here). Batch via blockIdx.z + strides.
// ---------------------------------------------------------------------------
template <bool TB>
__global__ __launch_bounds__(256)
void gemm_kernel(const float* __restrict__ A, const float* __restrict__ B,
                 float* __restrict__ C, int K, int lda, int ldb, int ldc,
                 size_t sA, size_t sB, size_t sC)
{
    constexpr int BM = 128, BN = 128, BK = 16;
    __shared__ float As[BK][BM];
    __shared__ float Bs[BK][BN];

    A += (size_t)blockIdx.z * sA;
    B += (size_t)blockIdx.z * sB;
    C += (size_t)blockIdx.z * sC;

    const int bm = blockIdx.y * BM;
    const int bn = blockIdx.x * BN;
    const int tid = threadIdx.x;
    const int tx = tid & 15;          // 0..15 -> N microtile
    const int ty = tid >> 4;          // 0..15 -> M microtile

    float acc[8][8];
#pragma unroll
    for (int i = 0; i < 8; i++)
#pragma unroll
        for (int j = 0; j < 8; j++) acc[i][j] = 0.0f;

    for (int k0 = 0; k0 < K; k0 += BK) {
        // ---- load A tile (row-major [M,K]) transposed into As[k][m] ----
#pragma unroll
        for (int it = 0; it < 2; it++) {
            int idx = tid + 256 * it;          // 0..511 (512 float4s)
            int row = idx >> 2;                // 0..127
            int kq  = (idx & 3) * 4;           // 0,4,8,12
            float4 v = *(const float4*)(A + (size_t)(bm + row) * lda + k0 + kq);
            As[kq + 0][row] = v.x;
            As[kq + 1][row] = v.y;
            As[kq + 2][row] = v.z;
            As[kq + 3][row] = v.w;
        }
        // ---- load B tile into Bs[k][n] ----
        if (TB) {
            // B stored [N,K]: transpose on load
#pragma unroll
            for (int it = 0; it < 2; it++) {
                int idx = tid + 256 * it;
                int row = idx >> 2;            // n: 0..127
                int kq  = (idx & 3) * 4;
                float4 v = *(const float4*)(B + (size_t)(bn + row) * ldb + k0 + kq);
                Bs[kq + 0][row] = v.x;
                Bs[kq + 1][row] = v.y;
                Bs[kq + 2][row] = v.z;
                Bs[kq + 3][row] = v.w;
            }
        } else {
            // B stored [K,N]: direct vectorized copy
#pragma unroll
            for (int it = 0; it < 2; it++) {
                int idx = tid + 256 * it;
                int kk = idx >> 5;             // 0..15
                int n4 = (idx & 31) * 4;       // 0..124
                *(float4*)&Bs[kk][n4] =
                    *(const float4*)(B + (size_t)(k0 + kk) * ldb + bn + n4);
            }
        }
        __syncthreads();

#pragma unroll
        for (int kk = 0; kk < BK; kk++) {
            float a[8], b[8];
            *(float4*)&a[0] = *(const float4*)&As[kk][ty * 8];
            *(float4*)&a[4] = *(const float4*)&As[kk][ty * 8 + 4];
            *(float4*)&b[0] = *(const float4*)&Bs[kk][tx * 8];
            *(float4*)&b[4] = *(const float4*)&Bs[kk][tx * 8 + 4];
#pragma unroll
            for (int i = 0; i < 8; i++)
#pragma unroll
                for (int j = 0; j < 8; j++) acc[i][j] += a[i] * b[j];
        }
        __syncthreads();
    }

#pragma unroll
    for (int i = 0; i < 8; i++) {
        float* cp = C + (size_t)(bm + ty * 8 + i) * ldc + bn + tx * 8;
        *(float4*)(cp + 0) = make_float4(acc[i][0], acc[i][1], acc[i][2], acc[i][3]);
        *(float4*)(cp + 4) = make_float4(acc[i][4], acc[i][5], acc[i][6], acc[i][7]);
    }
}

// ---------------------------------------------------------------------------
// S partials: Spart[sp][bh][i][j] = sum over 256 rows of K_bh[m,i]*V_bh[m,j]
// grid (32, SPLITS), 256 threads, 4x4 microtile over the 64x64 output.
// No atomics -> deterministic.
// ---------------------------------------------------------------------------
__global__ __launch_bounds__(256)
void s_partial_kernel()
{
    const int bh = blockIdx.x;            // 0..31
    const int sp = blockIdx.y;            // 0..SPLITS-1
    const int b  = bh >> 4;
    const int h  = bh & 15;
    const int rows_per = MSEQ / SPLITS;   // 256

    const float* Kp = g_K + ((size_t)(b * MSEQ + sp * rows_per)) * HIDD + h * DHEAD;
    const float* Vp = g_V + ((size_t)(b * MSEQ + sp * rows_per)) * HIDD + h * DHEAD;

    __shared__ float Ks[32][DHEAD];
    __shared__ float Vs[32][DHEAD];

    const int tid = threadIdx.x;
    const int i4 = (tid & 15) * 4;        // 0..60
    const int j4 = (tid >> 4) * 4;        // 0..60

    float acc[4][4];
#pragma unroll
    for (int i = 0; i < 4; i++)
#pragma unroll
        for (int j = 0; j < 4; j++) acc[i][j] = 0.0f;

    for (int r0 = 0; r0 < rows_per; r0 += 32) {
        // 32 rows x 64 cols = 512 float4 each for K and V; 2 per thread.
#pragma unroll
        for (int it = 0; it < 2; it++) {
            int idx = tid + 256 * it;      // 0..511
            int row = idx >> 4;            // 0..31
            int c4  = (idx & 15) * 4;      // 0..60
            *(float4*)&Ks[row][c4] = *(const float4*)(Kp + (size_t)(r0 + row) * HIDD + c4);
            *(float4*)&Vs[row][c4] = *(const float4*)(Vp + (size_t)(r0 + row) * HIDD + c4);
        }
        __syncthreads();
#pragma unroll
        for (int r = 0; r < 32; r++) {
            float kf[4], vf[4];
            *(float4*)kf = *(const float4*)&Ks[r][i4];
            *(float4*)vf = *(const float4*)&Vs[r][j4];
#pragma unroll
            for (int i = 0; i < 4; i++)
#pragma unroll
                for (int j = 0; j < 4; j++) acc[i][j] += kf[i] * vf[j];
        }
        __syncthreads();
    }

    float* Sp = g_Spart + (((size_t)sp * 32 + bh) * DHEAD) * DHEAD;
#pragma unroll
    for (int i = 0; i < 4; i++) {
        *(float4*)(Sp + (size_t)(i4 + i) * DHEAD + j4) =
            make_float4(acc[i][0], acc[i][1], acc[i][2], acc[i][3]);
    }
}

// ---------------------------------------------------------------------------
// U kernel: U[b][k][h*64+j] = sum_i Wq[h*64+i][k] * S_bh[i][j]
// grid (32 bh, 4 ksplit), 256 threads; one k per thread; S reads are
// uniform across the warp (shared-mem broadcast).
// ---------------------------------------------------------------------------
__global__ __launch_bounds__(256)
void u_kernel(const float* __restrict__ Wq)
{
    const int bh = blockIdx.x;
    const int b  = bh >> 4;
    const int h  = bh & 15;
    const int k  = blockIdx.y * 256 + threadIdx.x;  // 0..1023

    __shared__ float Ss[DHEAD][DHEAD];
    // Sum the SPLITS partials while staging into shared.
    for (int e = threadIdx.x; e < DHEAD * DHEAD; e += 256) {
        float s = 0.0f;
#pragma unroll
        for (int sp = 0; sp < SPLITS; sp++)
            s += g_Spart[((size_t)sp * 32 + bh) * (DHEAD * DHEAD) + e];
        ((float*)Ss)[e] = s;
    }
    __syncthreads();

    float acc[DHEAD];
#pragma unroll
    for (int j = 0; j < DHEAD; j++) acc[j] = 0.0f;

    for (int i = 0; i < DHEAD; i++) {
        float w = Wq[(size_t)(h * DHEAD + i) * HIDD + k];
#pragma unroll
        for (int j4 = 0; j4 < DHEAD; j4 += 4) {
            float4 sv = *(const float4*)&Ss[i][j4];
            acc[j4 + 0] += w * sv.x;
            acc[j4 + 1] += w * sv.y;
            acc[j4 + 2] += w * sv.z;
            acc[j4 + 3] += w * sv.w;
        }
    }

    float* Up = g_U + ((size_t)b * HIDD + k) * HIDD + h * DHEAD;
#pragma unroll
    for (int j = 0; j < DHEAD; j += 4)
        *(float4*)(Up + j) = make_float4(acc[j], acc[j + 1], acc[j + 2], acc[j + 3]);
}

// ---------------------------------------------------------------------------
// Launch: K,V projections -> S partials -> U -> C = U Wo^T -> out = h C
// ---------------------------------------------------------------------------
extern "C" void kernel_launch(void* const* d_in, const int* in_sizes, int n_in,
                              void* d_out, int out_size)
{
    const float* h  = (const float*)d_in[0];
    // d_in[1] = key_pe: dead branch in the reference, unused.
    const float* Wq = (const float*)d_in[2];
    const float* Wk = (const float*)d_in[3];
    const float* Wv = (const float*)d_in[4];
    const float* Wo = (const float*)d_in[5];
    float* out = (float*)d_out;

    float *Kp, *Vp, *Up, *Cp;
    cudaGetSymbolAddress((void**)&Kp, g_K);
    cudaGetSymbolAddress((void**)&Vp, g_V);
    cudaGetSymbolAddress((void**)&Up, g_U);
    cudaGetSymbolAddress((void**)&Cp, g_C);

    const dim3 blk(256);
    const size_t HH = (size_t)HIDD * HIDD;       // 1M
    const size_t MH = (size_t)MSEQ * HIDD;       // 2M

    // K = h Wk^T   (treat both batches as one 4096x1024 GEMM; weights shared)
    gemm_kernel<true><<<dim3(HIDD / 128, (NBATCH * MSEQ) / 128, 1), blk>>>(
        h, Wk, Kp, HIDD, HIDD, HIDD, HIDD, 0, 0, 0);
    // V = h Wv^T
    gemm_kernel<true><<<dim3(HIDD / 128, (NBATCH * MSEQ) / 128, 1), blk>>>(
        h, Wv, Vp, HIDD, HIDD, HIDD, HIDD, 0, 0, 0);

    // S partials: per (b,h), split-K over sequence
    s_partial_kernel<<<dim3(NBATCH * NHEAD, SPLITS), blk>>>();

    // U_b[:, hD:+D] = Wq_h^T S_bh
    u_kernel<<<dim3(NBATCH * NHEAD, HIDD / 256), blk>>>(Wq);

    // C_b = U_b Wo^T   (batched over z)
    gemm_kernel<true><<<dim3(HIDD / 128, HIDD / 128, NBATCH), blk>>>(
        Up, Wo, Cp, HIDD, HIDD, HIDD, HIDD, HH, 0, HH);

    // out_b = h_b C_b  (batched over z)
    gemm_kernel<false><<<dim3(HIDD / 128, MSEQ / 128, NBATCH), blk>>>(
        h, Cp, out, HIDD, HIDD, HIDD, HIDD, MH, HH, MH);
}

// round 7
// speedup vs baseline: 1.5333x; 1.5333x over previous
#include <cuda_runtime.h>
#include <cuda_bf16.h>
#include <cstdint>

// B=2, M=2048, HID=1024, NH=16, D=64.  No softmax in the reference =>
//   S_bh = K_bh^T V_bh (64x64);  U_b[:,hD:+D] = Wq_h^T S_bh;
//   C_b = U_b Wo^T;  out_b = h_b C_b.
// Big GEMMs (K,V,C,final ~30GF) run on tensor cores via bf16x3 split:
//   A*B ~= Ah*Bh + Ah*Bl + Al*Bh   (residual ~2^-16, rel_err ~3e-4)

#define HIDD   1024
#define MSEQ   2048
#define NBATCH 2
#define NHEAD  16
#define DHEAD  64
#define SPLITS 8

typedef __nv_bfloat16 bf16;

// ---------------- device scratch (no allocation allowed) ----------------
__device__ float g_K[NBATCH * MSEQ * HIDD];                        // fp32 K
__device__ float g_V[NBATCH * MSEQ * HIDD];                        // fp32 V
__device__ float g_Spart[SPLITS * NBATCH * NHEAD * DHEAD * DHEAD];
__device__ bf16 g_hh[NBATCH * MSEQ * HIDD], g_hl[NBATCH * MSEQ * HIDD];
__device__ bf16 g_wkh[HIDD * HIDD], g_wkl[HIDD * HIDD];
__device__ bf16 g_wvh[HIDD * HIDD], g_wvl[HIDD * HIDD];
__device__ bf16 g_woh[HIDD * HIDD], g_wol[HIDD * HIDD];
__device__ bf16 g_Uh[NBATCH * HIDD * HIDD], g_Ul[NBATCH * HIDD * HIDD];
__device__ bf16 g_Ch[NBATCH * HIDD * HIDD], g_Cl[NBATCH * HIDD * HIDD];

// ---------------- helpers ----------------
__device__ __forceinline__ void split2(float x, bf16& hi, bf16& lo) {
    hi = __float2bfloat16(x);
    lo = __float2bfloat16(x - __bfloat162float(hi));
}

__device__ __forceinline__ void ldsm4(uint32_t* r, const bf16* p) {
    uint32_t sa = (uint32_t)__cvta_generic_to_shared(p);
    asm volatile("ldmatrix.sync.aligned.m8n8.x4.shared.b16 {%0,%1,%2,%3}, [%4];"
                 : "=r"(r[0]), "=r"(r[1]), "=r"(r[2]), "=r"(r[3]) : "r"(sa));
}

__device__ __forceinline__ void mma_bf16(float* d, const uint32_t* a,
                                         uint32_t b0, uint32_t b1) {
    asm volatile(
        "mma.sync.aligned.m16n8k16.row.col.f32.bf16.bf16.f32 "
        "{%0,%1,%2,%3}, {%4,%5,%6,%7}, {%8,%9}, {%0,%1,%2,%3};"
        : "+f"(d[0]), "+f"(d[1]), "+f"(d[2]), "+f"(d[3])
        : "r"(a[0]), "r"(a[1]), "r"(a[2]), "r"(a[3]), "r"(b0), "r"(b1));
}

// ---------------- split fp32 -> (hi, lo) bf16 planes ----------------
__global__ __launch_bounds__(256)
void split_kernel(const float4* __restrict__ x, __nv_bfloat162* __restrict__ hi,
                  __nv_bfloat162* __restrict__ lo, int n4) {
    int i = blockIdx.x * 256 + threadIdx.x;
    if (i >= n4) return;
    float4 v = x[i];
    bf16 h0, l0, h1, l1, h2, l2, h3, l3;
    split2(v.x, h0, l0); split2(v.y, h1, l1);
    split2(v.z, h2, l2); split2(v.w, h3, l3);
    hi[2 * i]     = __nv_bfloat162(h0, h1);
    hi[2 * i + 1] = __nv_bfloat162(h2, h3);
    lo[2 * i]     = __nv_bfloat162(l0, l1);
    lo[2 * i + 1] = __nv_bfloat162(l2, l3);
}

// ---------------- bf16x3 tensor-core GEMM ----------------
// C[M,N] = A[M,K] * op(B), fp32 result.
// TB=true : B stored [N,K] row-major (op = B^T)
// TB=false: B stored [K,N] row-major (op = B)
// OSPLIT  : emit (hi,lo) bf16 planes instead of fp32.
// CTA tile 128x128x32, 8 warps (warp tile 64x32). All dims multiples.
#define SROW 40   // smem row stride in bf16 (80B: conflict-free for ldmatrix)

template <bool TB, bool OSPLIT>
__global__ __launch_bounds__(256)
void gemm3(const bf16* __restrict__ Ah, const bf16* __restrict__ Al,
           const bf16* __restrict__ Bh, const bf16* __restrict__ Bl,
           float* __restrict__ Cf, bf16* __restrict__ Ch, bf16* __restrict__ Cl,
           int K, int lda, int ldb, int ldc, size_t sA, size_t sB, size_t sC)
{
    __shared__ __align__(16) bf16 As[2][128 * SROW];
    __shared__ __align__(16) bf16 Bs[2][128 * SROW];

    Ah += (size_t)blockIdx.z * sA;  Al += (size_t)blockIdx.z * sA;
    Bh += (size_t)blockIdx.z * sB;  Bl += (size_t)blockIdx.z * sB;
    if (OSPLIT) { Ch += (size_t)blockIdx.z * sC; Cl += (size_t)blockIdx.z * sC; }
    else        { Cf += (size_t)blockIdx.z * sC; }

    const int bm = blockIdx.y * 128;
    const int bn = blockIdx.x * 128;
    const int tid = threadIdx.x;
    const int lane = tid & 31;
    const int wid = tid >> 5;
    const int wm = (wid >> 2) * 64;   // 0, 64
    const int wn = (wid & 3) * 32;    // 0,32,64,96

    float acc[4][4][4];
#pragma unroll
    for (int mi = 0; mi < 4; mi++)
#pragma unroll
        for (int ni = 0; ni < 4; ni++)
#pragma unroll
            for (int r = 0; r < 4; r++) acc[mi][ni][r] = 0.0f;

    const bf16* Asrc[2] = {Ah, Al};
    const bf16* Bsrc[2] = {Bh, Bl};

    for (int k0 = 0; k0 < K; k0 += 32) {
        // stage A: [128 rows x 32 k] per plane
#pragma unroll
        for (int p = 0; p < 2; p++) {
#pragma unroll
            for (int it = 0; it < 2; it++) {
                int idx = tid + 256 * it;          // 0..511
                int r = idx >> 2;                  // 0..127
                int c8 = (idx & 3) * 8;            // 0,8,16,24
                uint4 v = *(const uint4*)(Asrc[p] + (size_t)(bm + r) * lda + k0 + c8);
                *(uint2*)&As[p][r * SROW + c8]     = make_uint2(v.x, v.y);
                *(uint2*)&As[p][r * SROW + c8 + 4] = make_uint2(v.z, v.w);
            }
        }
        // stage B into Bs[n][k]
        if (TB) {
#pragma unroll
            for (int p = 0; p < 2; p++) {
#pragma unroll
                for (int it = 0; it < 2; it++) {
                    int idx = tid + 256 * it;
                    int r = idx >> 2;              // n row 0..127
                    int c8 = (idx & 3) * 8;
                    uint4 v = *(const uint4*)(Bsrc[p] + (size_t)(bn + r) * ldb + k0 + c8);
                    *(uint2*)&Bs[p][r * SROW + c8]     = make_uint2(v.x, v.y);
                    *(uint2*)&Bs[p][r * SROW + c8 + 4] = make_uint2(v.z, v.w);
                }
            }
        } else {
            // B stored [K,N]: transpose on stage
#pragma unroll
            for (int p = 0; p < 2; p++) {
#pragma unroll
                for (int it = 0; it < 2; it++) {
                    int idx = tid + 256 * it;      // 0..511
                    int kr = idx >> 4;             // 0..31
                    int nc = (idx & 15) * 8;       // 0..120
                    uint4 v = *(const uint4*)(Bsrc[p] + (size_t)(k0 + kr) * ldb + bn + nc);
                    const bf16* pv = (const bf16*)&v;
#pragma unroll
                    for (int j = 0; j < 8; j++)
                        Bs[p][(nc + j) * SROW + kr] = pv[j];
                }
            }
        }
        __syncthreads();

#pragma unroll
        for (int kk = 0; kk < 32; kk += 16) {
            uint32_t aH[4][4], aL[4][4], bH[2][4], bL[2][4];
            const int rlane = lane & 15;
            const int koff = kk + (lane >> 4) * 8;
#pragma unroll
            for (int mi = 0; mi < 4; mi++) {
                const int row = wm + mi * 16 + rlane;
                ldsm4(aH[mi], &As[0][row * SROW + koff]);
                ldsm4(aL[mi], &As[1][row * SROW + koff]);
            }
#pragma unroll
            for (int nb = 0; nb < 2; nb++) {
                const int row = wn + nb * 16 + rlane;
                ldsm4(bH[nb], &Bs[0][row * SROW + koff]);
                ldsm4(bL[nb], &Bs[1][row * SROW + koff]);
            }
#pragma unroll
            for (int mi = 0; mi < 4; mi++) {
#pragma unroll
                for (int ni = 0; ni < 4; ni++) {
                    const int nb = ni >> 1, sub = ni & 1;
                    mma_bf16(acc[mi][ni], aH[mi], bH[nb][sub], bH[nb][sub + 2]);
                    mma_bf16(acc[mi][ni], aH[mi], bL[nb][sub], bL[nb][sub + 2]);
                    mma_bf16(acc[mi][ni], aL[mi], bH[nb][sub], bH[nb][sub + 2]);
                }
            }
        }
        __syncthreads();
    }

    // epilogue: c0:(g,2c) c1:(g,2c+1) c2:(g+8,2c) c3:(g+8,2c+1)
    const int g = lane >> 2;
    const int c2 = (lane & 3) * 2;
#pragma unroll
    for (int mi = 0; mi < 4; mi++) {
#pragma unroll
        for (int ni = 0; ni < 4; ni++) {
            int row0 = bm + wm + mi * 16 + g;
            int col  = bn + wn + ni * 8 + c2;
            float* a = acc[mi][ni];
            if (OSPLIT) {
                bf16 h0, l0, h1, l1;
                split2(a[0], h0, l0); split2(a[1], h1, l1);
                *(__nv_bfloat162*)(Ch + (size_t)row0 * ldc + col) = __nv_bfloat162(h0, h1);
                *(__nv_bfloat162*)(Cl + (size_t)row0 * ldc + col) = __nv_bfloat162(l0, l1);
                split2(a[2], h0, l0); split2(a[3], h1, l1);
                *(__nv_bfloat162*)(Ch + (size_t)(row0 + 8) * ldc + col) = __nv_bfloat162(h0, h1);
                *(__nv_bfloat162*)(Cl + (size_t)(row0 + 8) * ldc + col) = __nv_bfloat162(l0, l1);
            } else {
                *(float2*)(Cf + (size_t)row0 * ldc + col)       = make_float2(a[0], a[1]);
                *(float2*)(Cf + (size_t)(row0 + 8) * ldc + col) = make_float2(a[2], a[3]);
            }
        }
    }
}

// ---------------- S partials: Spart[sp][bh] = sum_rows K^T V ----------------
__global__ __launch_bounds__(256)
void s_partial_kernel()
{
    const int bh = blockIdx.x, sp = blockIdx.y;
    const int b = bh >> 4, h = bh & 15;
    const int rows_per = MSEQ / SPLITS;   // 256

    const float* Kp = g_K + ((size_t)(b * MSEQ + sp * rows_per)) * HIDD + h * DHEAD;
    const float* Vp = g_V + ((size_t)(b * MSEQ + sp * rows_per)) * HIDD + h * DHEAD;

    __shared__ float Ks[32][DHEAD];
    __shared__ float Vs[32][DHEAD];

    const int tid = threadIdx.x;
    const int i4 = (tid & 15) * 4, j4 = (tid >> 4) * 4;

    float acc[4][4];
#pragma unroll
    for (int i = 0; i < 4; i++)
#pragma unroll
        for (int j = 0; j < 4; j++) acc[i][j] = 0.0f;

    for (int r0 = 0; r0 < rows_per; r0 += 32) {
#pragma unroll
        for (int it = 0; it < 2; it++) {
            int idx = tid + 256 * it;
            int row = idx >> 4, c4 = (idx & 15) * 4;
            *(float4*)&Ks[row][c4] = *(const float4*)(Kp + (size_t)(r0 + row) * HIDD + c4);
            *(float4*)&Vs[row][c4] = *(const float4*)(Vp + (size_t)(r0 + row) * HIDD + c4);
        }
        __syncthreads();
#pragma unroll
        for (int r = 0; r < 32; r++) {
            float kf[4], vf[4];
            *(float4*)kf = *(const float4*)&Ks[r][i4];
            *(float4*)vf = *(const float4*)&Vs[r][j4];
#pragma unroll
            for (int i = 0; i < 4; i++)
#pragma unroll
                for (int j = 0; j < 4; j++) acc[i][j] += kf[i] * vf[j];
        }
        __syncthreads();
    }

    float* Sp = g_Spart + (((size_t)sp * 32 + bh) * DHEAD) * DHEAD;
#pragma unroll
    for (int i = 0; i < 4; i++)
        *(float4*)(Sp + (size_t)(i4 + i) * DHEAD + j4) =
            make_float4(acc[i][0], acc[i][1], acc[i][2], acc[i][3]);
}

// ---------------- U: U[b][k][h*64+j] = sum_i Wq[h*64+i][k]*S_bh[i][j] ------
// j split across blockIdx.z (32 cols each) for occupancy; writes hi/lo planes.
__global__ __launch_bounds__(256)
void u_kernel(const float* __restrict__ Wq)
{
    const int bh = blockIdx.x;
    const int b = bh >> 4, h = bh & 15;
    const int k = blockIdx.y * 256 + threadIdx.x;
    const int j0 = blockIdx.z * 32;

    __shared__ float Ss[DHEAD][32];
    for (int e = threadIdx.x; e < DHEAD * 32; e += 256) {
        int i = e >> 5, j = e & 31;
        float s = 0.0f;
#pragma unroll
        for (int sp = 0; sp < SPLITS; sp++)
            s += g_Spart[((size_t)sp * 32 + bh) * (DHEAD * DHEAD) + i * DHEAD + j0 + j];
        Ss[i][j] = s;
    }
    __syncthreads();

    float acc[32];
#pragma unroll
    for (int j = 0; j < 32; j++) acc[j] = 0.0f;

#pragma unroll 4
    for (int i = 0; i < DHEAD; i++) {
        float w = Wq[(size_t)(h * DHEAD + i) * HIDD + k];
#pragma unroll
        for (int j = 0; j < 32; j += 4) {
            float4 sv = *(const float4*)&Ss[i][j];
            acc[j + 0] += w * sv.x; acc[j + 1] += w * sv.y;
            acc[j + 2] += w * sv.z; acc[j + 3] += w * sv.w;
        }
    }

    size_t base = ((size_t)b * HIDD + k) * HIDD + h * DHEAD + j0;
#pragma unroll
    for (int j = 0; j < 32; j += 2) {
        bf16 h0, l0, h1, l1;
        split2(acc[j], h0, l0); split2(acc[j + 1], h1, l1);
        *(__nv_bfloat162*)(g_Uh + base + j) = __nv_bfloat162(h0, h1);
        *(__nv_bfloat162*)(g_Ul + base + j) = __nv_bfloat162(l0, l1);
    }
}

// ---------------- launch ----------------
extern "C" void kernel_launch(void* const* d_in, const int* in_sizes, int n_in,
                              void* d_out, int out_size)
{
    const float* h  = (const float*)d_in[0];
    // d_in[1] = key_pe: dead branch in reference, unused.
    const float* Wq = (const float*)d_in[2];
    const float* Wk = (const float*)d_in[3];
    const float* Wv = (const float*)d_in[4];
    const float* Wo = (const float*)d_in[5];
    float* out = (float*)d_out;

    float *Kp, *Vp;
    bf16 *hh, *hl, *wkh, *wkl, *wvh, *wvl, *woh, *wol, *Uh, *Ul, *Ch, *Cl;
    cudaGetSymbolAddress((void**)&Kp, g_K);
    cudaGetSymbolAddress((void**)&Vp, g_V);
    cudaGetSymbolAddress((void**)&hh, g_hh);   cudaGetSymbolAddress((void**)&hl, g_hl);
    cudaGetSymbolAddress((void**)&wkh, g_wkh); cudaGetSymbolAddress((void**)&wkl, g_wkl);
    cudaGetSymbolAddress((void**)&wvh, g_wvh); cudaGetSymbolAddress((void**)&wvl, g_wvl);
    cudaGetSymbolAddress((void**)&woh, g_woh); cudaGetSymbolAddress((void**)&wol, g_wol);
    cudaGetSymbolAddress((void**)&Uh, g_Uh);   cudaGetSymbolAddress((void**)&Ul, g_Ul);
    cudaGetSymbolAddress((void**)&Ch, g_Ch);   cudaGetSymbolAddress((void**)&Cl, g_Cl);

    const dim3 blk(256);
    const size_t HH = (size_t)HIDD * HIDD;   // 1M
    const size_t MH = (size_t)MSEQ * HIDD;   // 2M
    const int nh4 = (NBATCH * MSEQ * HIDD) / 4;
    const int nw4 = (HIDD * HIDD) / 4;

    // split inputs into bf16 hi/lo planes
    split_kernel<<<(nh4 + 255) / 256, blk>>>((const float4*)h,
        (__nv_bfloat162*)hh, (__nv_bfloat162*)hl, nh4);
    split_kernel<<<(nw4 + 255) / 256, blk>>>((const float4*)Wk,
        (__nv_bfloat162*)wkh, (__nv_bfloat162*)wkl, nw4);
    split_kernel<<<(nw4 + 255) / 256, blk>>>((const float4*)Wv,
        (__nv_bfloat162*)wvh, (__nv_bfloat162*)wvl, nw4);
    split_kernel<<<(nw4 + 255) / 256, blk>>>((const float4*)Wo,
        (__nv_bfloat162*)woh, (__nv_bfloat162*)wol, nw4);

    // K = h Wk^T, V = h Wv^T  (batches fused: M=4096)
    gemm3<true, false><<<dim3(HIDD / 128, (NBATCH * MSEQ) / 128, 1), blk>>>(
        hh, hl, wkh, wkl, Kp, nullptr, nullptr, HIDD, HIDD, HIDD, HIDD, 0, 0, 0);
    gemm3<true, false><<<dim3(HIDD / 128, (NBATCH * MSEQ) / 128, 1), blk>>>(
        hh, hl, wvh, wvl, Vp, nullptr, nullptr, HIDD, HIDD, HIDD, HIDD, 0, 0, 0);

    // S partials (fp32, deterministic split-K)
    s_partial_kernel<<<dim3(NBATCH * NHEAD, SPLITS), blk>>>();

    // U (fp32 compute, bf16 hi/lo output)
    u_kernel<<<dim3(NBATCH * NHEAD, HIDD / 256, 2), blk>>>(Wq);

    // C_b = U_b Wo^T  -> bf16 hi/lo planes
    gemm3<true, true><<<dim3(HIDD / 128, HIDD / 128, NBATCH), blk>>>(
        Uh, Ul, woh, wol, nullptr, Ch, Cl, HIDD, HIDD, HIDD, HIDD, HH, 0, HH);

    // out_b = h_b C_b  (B is [K,N])
    gemm3<false, false><<<dim3(HIDD / 128, MSEQ / 128, NBATCH), blk>>>(
        hh, hl, Ch, Cl, out, nullptr, nullptr, HIDD, HIDD, HIDD, HIDD, MH, HH, MH);
}

// round 10
// speedup vs baseline: 2.3693x; 1.5453x over previous
#include <cuda_runtime.h>
#include <cuda_bf16.h>
#include <cstdint>

// B=2, M=2048, HID=1024, NH=16, D=64.  Reference has NO softmax =>
//   S_bh = K_bh^T V_bh (64x64);  U_b[:,hD:+D] = Wq_h^T S_bh;
//   Ct_b[n,k] = sum_j Wo[n,j] U_b[k,j];  out_b[m,n] = sum_k h[m,k] Ct_b[n,k].
// All 4 big GEMMs are D = A * B^T with K-major operands.
// fp32 via bf16x3 split on mma.sync (tcgen05 unavailable: harness PTX targets
// compute_103, which rejects tcgen05.*):  A*B ~= Ah*Bh + Ah*Bl + Al*Bh.

#define HIDD   1024
#define MSEQ   2048
#define NBATCH 2
#define NHEAD  16
#define DHEAD  64
#define SPLITS 8

typedef __nv_bfloat16 bf16;

// ---------------- device scratch ----------------
__device__ float g_K[NBATCH * MSEQ * HIDD];
__device__ float g_V[NBATCH * MSEQ * HIDD];
__device__ float g_Spart[SPLITS * NBATCH * NHEAD * DHEAD * DHEAD];
__device__ bf16 g_hh[NBATCH * MSEQ * HIDD], g_hl[NBATCH * MSEQ * HIDD];
__device__ bf16 g_wkh[HIDD * HIDD], g_wkl[HIDD * HIDD];
__device__ bf16 g_wvh[HIDD * HIDD], g_wvl[HIDD * HIDD];
__device__ bf16 g_woh[HIDD * HIDD], g_wol[HIDD * HIDD];
__device__ bf16 g_Uh[NBATCH * HIDD * HIDD], g_Ul[NBATCH * HIDD * HIDD];
__device__ bf16 g_Cth[NBATCH * HIDD * HIDD], g_Ctl[NBATCH * HIDD * HIDD];

// ---------------- helpers ----------------
__device__ __forceinline__ void split2(float x, bf16& hi, bf16& lo) {
    hi = __float2bfloat16(x);
    lo = __float2bfloat16(x - __bfloat162float(hi));
}

// SW64-style 16B-chunk swizzle for 64-byte rows: phases all-distinct across
// any 8 consecutive rows at fixed column -> conflict-free ldmatrix.
__device__ __forceinline__ uint32_t swz(uint32_t off) {
    return off ^ ((off >> 3) & 0x30);
}

__device__ __forceinline__ void ldsm4(uint32_t* r, uint32_t sa) {
    asm volatile("ldmatrix.sync.aligned.m8n8.x4.shared.b16 {%0,%1,%2,%3}, [%4];"
                 : "=r"(r[0]), "=r"(r[1]), "=r"(r[2]), "=r"(r[3]) : "r"(sa));
}

__device__ __forceinline__ void mma_bf16(float* d, const uint32_t* a,
                                         uint32_t b0, uint32_t b1) {
    asm volatile(
        "mma.sync.aligned.m16n8k16.row.col.f32.bf16.bf16.f32 "
        "{%0,%1,%2,%3}, {%4,%5,%6,%7}, {%8,%9}, {%0,%1,%2,%3};"
        : "+f"(d[0]), "+f"(d[1]), "+f"(d[2]), "+f"(d[3])
        : "r"(a[0]), "r"(a[1]), "r"(a[2]), "r"(a[3]), "r"(b0), "r"(b1));
}

__device__ __forceinline__ void cp16(uint32_t d, const void* s) {
    asm volatile("cp.async.cg.shared.global [%0], [%1], 16;" :: "r"(d), "l"(s));
}

// ---------------- split fp32 -> (hi, lo) bf16 planes ----------------
__global__ __launch_bounds__(256)
void split_kernel(const float4* __restrict__ x, __nv_bfloat162* __restrict__ hi,
                  __nv_bfloat162* __restrict__ lo, int n4) {
    int i = blockIdx.x * 256 + threadIdx.x;
    if (i >= n4) return;
    float4 v = x[i];
    bf16 h0, l0, h1, l1, h2, l2, h3, l3;
    split2(v.x, h0, l0); split2(v.y, h1, l1);
    split2(v.z, h2, l2); split2(v.w, h3, l3);
    hi[2 * i]     = __nv_bfloat162(h0, h1);
    hi[2 * i + 1] = __nv_bfloat162(h2, h3);
    lo[2 * i]     = __nv_bfloat162(l0, l1);
    lo[2 * i + 1] = __nv_bfloat162(l2, l3);
}

// ---------------- bf16x3 mma.sync GEMM: D[128x128 tile] = A * B^T ----------
// A [M,1024] K-major, B [N,1024] K-major, K = 1024.
// 2-stage cp.async double buffer, BK=32. 8 warps, warp tile 64x32.
// Smem tile: 128 rows x 64B (32 bf16), SW64 swizzled. 8KB/tile, 4 tiles/buf.
#define TILE_B 8192
#define BUF_B  (4 * TILE_B)          // Ah, Al, Bh, Bl
#define DSM_SIZE (2 * BUF_B + 256)

// stage one 128x32-bf16 K-chunk into swizzled smem (2 cp.async per thread)
__device__ __forceinline__ void stage(uint32_t sb, const bf16* g, int tid) {
#pragma unroll
    for (int i = 0; i < 2; i++) {
        int idx = tid + 256 * i;           // 0..511
        int r = idx >> 2;                  // 0..127
        int c = (idx & 3) * 16;            // 0,16,32,48 bytes
        cp16(sb + swz((uint32_t)(r * 64 + c)),
             (const char*)g + (size_t)r * (HIDD * 2) + c);
    }
}

template <bool OSPLIT>
__global__ __launch_bounds__(256)
void gemm3(const bf16* __restrict__ Ah, const bf16* __restrict__ Al,
           const bf16* __restrict__ Bh, const bf16* __restrict__ Bl,
           float* __restrict__ Cf, bf16* __restrict__ Ch, bf16* __restrict__ Cl,
           size_t sA, size_t sB, size_t sC)
{
    extern __shared__ char dyn[];
    uint32_t dbase = (uint32_t)__cvta_generic_to_shared(dyn);
    dbase = (dbase + 255u) & ~255u;

    Ah += (size_t)blockIdx.z * sA;  Al += (size_t)blockIdx.z * sA;
    Bh += (size_t)blockIdx.z * sB;  Bl += (size_t)blockIdx.z * sB;
    if (OSPLIT) { Ch += (size_t)blockIdx.z * sC; Cl += (size_t)blockIdx.z * sC; }
    else        { Cf += (size_t)blockIdx.z * sC; }

    const int bm = blockIdx.y * 128;
    const int bn = blockIdx.x * 128;
    const int tid = threadIdx.x;
    const int lane = tid & 31;
    const int wid = tid >> 5;
    const int wm = (wid >> 2) * 64;    // 0, 64
    const int wn = (wid & 3) * 32;     // 0,32,64,96

    float acc[4][4][4];
#pragma unroll
    for (int mi = 0; mi < 4; mi++)
#pragma unroll
        for (int ni = 0; ni < 4; ni++)
#pragma unroll
            for (int r = 0; r < 4; r++) acc[mi][ni][r] = 0.0f;

    const bf16* Am = Ah + (size_t)bm * HIDD;
    const bf16* Alm = Al + (size_t)bm * HIDD;
    const bf16* Bm = Bh + (size_t)bn * HIDD;
    const bf16* Blm = Bl + (size_t)bn * HIDD;

    // prologue: stage k-chunk 0 into buffer 0
    stage(dbase,              Am,  tid);
    stage(dbase + TILE_B,     Alm, tid);
    stage(dbase + 2 * TILE_B, Bm,  tid);
    stage(dbase + 3 * TILE_B, Blm, tid);
    asm volatile("cp.async.commit_group;" ::: "memory");

    const int NIT = HIDD / 32;   // 32
    for (int it = 0; it < NIT; it++) {
        if (it + 1 < NIT) {
            const uint32_t bo = dbase + ((it + 1) & 1) * BUF_B;
            const int k0 = (it + 1) * 32;
            stage(bo,              Am + k0,  tid);
            stage(bo + TILE_B,     Alm + k0, tid);
            stage(bo + 2 * TILE_B, Bm + k0,  tid);
            stage(bo + 3 * TILE_B, Blm + k0, tid);
            asm volatile("cp.async.commit_group;" ::: "memory");
            asm volatile("cp.async.wait_group 1;" ::: "memory");
        } else {
            asm volatile("cp.async.wait_group 0;" ::: "memory");
        }
        __syncthreads();

        const uint32_t bo = dbase + (it & 1) * BUF_B;
        const int rlane = lane & 15;
        const int kbyte = (lane >> 4) * 16;   // 16B chunk select within k16
#pragma unroll
        for (int kk = 0; kk < 2; kk++) {      // two K=16 steps
            const uint32_t cbyte = kk * 32 + kbyte;
            uint32_t aH[4][4], aL[4][4], bH[2][4], bL[2][4];
#pragma unroll
            for (int mi = 0; mi < 4; mi++) {
                uint32_t off = (uint32_t)((wm + mi * 16 + rlane) * 64) + cbyte;
                ldsm4(aH[mi], bo + swz(off));
                ldsm4(aL[mi], bo + TILE_B + swz(off));
            }
#pragma unroll
            for (int nb = 0; nb < 2; nb++) {
                uint32_t off = (uint32_t)((wn + nb * 16 + rlane) * 64) + cbyte;
                ldsm4(bH[nb], bo + 2 * TILE_B + swz(off));
                ldsm4(bL[nb], bo + 3 * TILE_B + swz(off));
            }
            // plane-major: 16 independent MMAs between accumulator revisits
#pragma unroll
            for (int mi = 0; mi < 4; mi++)
#pragma unroll
                for (int ni = 0; ni < 4; ni++) {
                    const int nb = ni >> 1, sub = ni & 1;
                    mma_bf16(acc[mi][ni], aH[mi], bH[nb][sub], bH[nb][sub + 2]);
                }
#pragma unroll
            for (int mi = 0; mi < 4; mi++)
#pragma unroll
                for (int ni = 0; ni < 4; ni++) {
                    const int nb = ni >> 1, sub = ni & 1;
                    mma_bf16(acc[mi][ni], aH[mi], bL[nb][sub], bL[nb][sub + 2]);
                }
#pragma unroll
            for (int mi = 0; mi < 4; mi++)
#pragma unroll
                for (int ni = 0; ni < 4; ni++) {
                    const int nb = ni >> 1, sub = ni & 1;
                    mma_bf16(acc[mi][ni], aL[mi], bH[nb][sub], bH[nb][sub + 2]);
                }
        }
        __syncthreads();
    }

    // epilogue: c0:(g,2c) c1:(g,2c+1) c2:(g+8,2c) c3:(g+8,2c+1)
    const int g = lane >> 2;
    const int c2 = (lane & 3) * 2;
#pragma unroll
    for (int mi = 0; mi < 4; mi++) {
#pragma unroll
        for (int ni = 0; ni < 4; ni++) {
            int row0 = bm + wm + mi * 16 + g;
            int col  = bn + wn + ni * 8 + c2;
            float* a = acc[mi][ni];
            if (OSPLIT) {
                bf16 h0, l0, h1, l1;
                split2(a[0], h0, l0); split2(a[1], h1, l1);
                *(__nv_bfloat162*)(Ch + (size_t)row0 * HIDD + col) = __nv_bfloat162(h0, h1);
                *(__nv_bfloat162*)(Cl + (size_t)row0 * HIDD + col) = __nv_bfloat162(l0, l1);
                split2(a[2], h0, l0); split2(a[3], h1, l1);
                *(__nv_bfloat162*)(Ch + (size_t)(row0 + 8) * HIDD + col) = __nv_bfloat162(h0, h1);
                *(__nv_bfloat162*)(Cl + (size_t)(row0 + 8) * HIDD + col) = __nv_bfloat162(l0, l1);
            } else {
                *(float2*)(Cf + (size_t)row0 * HIDD + col)       = make_float2(a[0], a[1]);
                *(float2*)(Cf + (size_t)(row0 + 8) * HIDD + col) = make_float2(a[2], a[3]);
            }
        }
    }
}

// ---------------- S partials: Spart[sp][bh] = sum_rows K^T V ----------------
__global__ __launch_bounds__(256)
void s_partial_kernel()
{
    const int bh = blockIdx.x, sp = blockIdx.y;
    const int b = bh >> 4, h = bh & 15;
    const int rows_per = MSEQ / SPLITS;

    const float* Kp = g_K + ((size_t)(b * MSEQ + sp * rows_per)) * HIDD + h * DHEAD;
    const float* Vp = g_V + ((size_t)(b * MSEQ + sp * rows_per)) * HIDD + h * DHEAD;

    __shared__ float Ks[32][DHEAD];
    __shared__ float Vs[32][DHEAD];

    const int tid = threadIdx.x;
    const int i4 = (tid & 15) * 4, j4 = (tid >> 4) * 4;

    float acc[4][4];
#pragma unroll
    for (int i = 0; i < 4; i++)
#pragma unroll
        for (int j = 0; j < 4; j++) acc[i][j] = 0.0f;

    for (int r0 = 0; r0 < rows_per; r0 += 32) {
#pragma unroll
        for (int it = 0; it < 2; it++) {
            int idx = tid + 256 * it;
            int row = idx >> 4, c4 = (idx & 15) * 4;
            *(float4*)&Ks[row][c4] = *(const float4*)(Kp + (size_t)(r0 + row) * HIDD + c4);
            *(float4*)&Vs[row][c4] = *(const float4*)(Vp + (size_t)(r0 + row) * HIDD + c4);
        }
        __syncthreads();
#pragma unroll
        for (int r = 0; r < 32; r++) {
            float kf[4], vf[4];
            *(float4*)kf = *(const float4*)&Ks[r][i4];
            *(float4*)vf = *(const float4*)&Vs[r][j4];
#pragma unroll
            for (int i = 0; i < 4; i++)
#pragma unroll
                for (int j = 0; j < 4; j++) acc[i][j] += kf[i] * vf[j];
        }
        __syncthreads();
    }

    float* Sp = g_Spart + (((size_t)sp * 32 + bh) * DHEAD) * DHEAD;
#pragma unroll
    for (int i = 0; i < 4; i++)
        *(float4*)(Sp + (size_t)(i4 + i) * DHEAD + j4) =
            make_float4(acc[i][0], acc[i][1], acc[i][2], acc[i][3]);
}

// ---------------- U: U[b][k][h*64+j] = sum_i Wq[h*64+i][k]*S_bh[i][j] ------
__global__ __launch_bounds__(256)
void u_kernel(const float* __restrict__ Wq)
{
    const int bh = blockIdx.x;
    const int b = bh >> 4, h = bh & 15;
    const int k = blockIdx.y * 256 + threadIdx.x;
    const int j0 = blockIdx.z * 32;

    __shared__ float Ss[DHEAD][32];
    for (int e = threadIdx.x; e < DHEAD * 32; e += 256) {
        int i = e >> 5, j = e & 31;
        float s = 0.0f;
#pragma unroll
        for (int sp = 0; sp < SPLITS; sp++)
            s += g_Spart[((size_t)sp * 32 + bh) * (DHEAD * DHEAD) + i * DHEAD + j0 + j];
        Ss[i][j] = s;
    }
    __syncthreads();

    float acc[32];
#pragma unroll
    for (int j = 0; j < 32; j++) acc[j] = 0.0f;

#pragma unroll 4
    for (int i = 0; i < DHEAD; i++) {
        float w = Wq[(size_t)(h * DHEAD + i) * HIDD + k];
#pragma unroll
        for (int j = 0; j < 32; j += 4) {
            float4 sv = *(const float4*)&Ss[i][j];
            acc[j + 0] += w * sv.x; acc[j + 1] += w * sv.y;
            acc[j + 2] += w * sv.z; acc[j + 3] += w * sv.w;
        }
    }

    size_t base = ((size_t)b * HIDD + k) * HIDD + h * DHEAD + j0;
#pragma unroll
    for (int j = 0; j < 32; j += 2) {
        bf16 h0, l0, h1, l1;
        split2(acc[j], h0, l0); split2(acc[j + 1], h1, l1);
        *(__nv_bfloat162*)(g_Uh + base + j) = __nv_bfloat162(h0, h1);
        *(__nv_bfloat162*)(g_Ul + base + j) = __nv_bfloat162(l0, l1);
    }
}

// ---------------- launch ----------------
extern "C" void kernel_launch(void* const* d_in, const int* in_sizes, int n_in,
                              void* d_out, int out_size)
{
    const float* h  = (const float*)d_in[0];
    // d_in[1] = key_pe: dead branch in reference, unused.
    const float* Wq = (const float*)d_in[2];
    const float* Wk = (const float*)d_in[3];
    const float* Wv = (const float*)d_in[4];
    const float* Wo = (const float*)d_in[5];
    float* out = (float*)d_out;

    float *Kp, *Vp;
    bf16 *hh, *hl, *wkh, *wkl, *wvh, *wvl, *woh, *wol, *Uh, *Ul, *Cth, *Ctl;
    cudaGetSymbolAddress((void**)&Kp, g_K);
    cudaGetSymbolAddress((void**)&Vp, g_V);
    cudaGetSymbolAddress((void**)&hh, g_hh);   cudaGetSymbolAddress((void**)&hl, g_hl);
    cudaGetSymbolAddress((void**)&wkh, g_wkh); cudaGetSymbolAddress((void**)&wkl, g_wkl);
    cudaGetSymbolAddress((void**)&wvh, g_wvh); cudaGetSymbolAddress((void**)&wvl, g_wvl);
    cudaGetSymbolAddress((void**)&woh, g_woh); cudaGetSymbolAddress((void**)&wol, g_wol);
    cudaGetSymbolAddress((void**)&Uh, g_Uh);   cudaGetSymbolAddress((void**)&Ul, g_Ul);
    cudaGetSymbolAddress((void**)&Cth, g_Cth); cudaGetSymbolAddress((void**)&Ctl, g_Ctl);

    cudaFuncSetAttribute(gemm3<false>, cudaFuncAttributeMaxDynamicSharedMemorySize, DSM_SIZE);
    cudaFuncSetAttribute(gemm3<true>,  cudaFuncAttributeMaxDynamicSharedMemorySize, DSM_SIZE);

    const dim3 blk(256);
    const size_t HH = (size_t)HIDD * HIDD;
    const size_t MH = (size_t)MSEQ * HIDD;
    const int nh4 = (NBATCH * MSEQ * HIDD) / 4;
    const int nw4 = (HIDD * HIDD) / 4;

    split_kernel<<<(nh4 + 255) / 256, blk>>>((const float4*)h,
        (__nv_bfloat162*)hh, (__nv_bfloat162*)hl, nh4);
    split_kernel<<<(nw4 + 255) / 256, blk>>>((const float4*)Wk,
        (__nv_bfloat162*)wkh, (__nv_bfloat162*)wkl, nw4);
    split_kernel<<<(nw4 + 255) / 256, blk>>>((const float4*)Wv,
        (__nv_bfloat162*)wvh, (__nv_bfloat162*)wvl, nw4);
    split_kernel<<<(nw4 + 255) / 256, blk>>>((const float4*)Wo,
        (__nv_bfloat162*)woh, (__nv_bfloat162*)wol, nw4);

    // K = h Wk^T, V = h Wv^T (batches fused: M=4096 rows)
    gemm3<false><<<dim3(HIDD / 128, (NBATCH * MSEQ) / 128, 1), blk, DSM_SIZE>>>(
        hh, hl, wkh, wkl, Kp, nullptr, nullptr, 0, 0, 0);
    gemm3<false><<<dim3(HIDD / 128, (NBATCH * MSEQ) / 128, 1), blk, DSM_SIZE>>>(
        hh, hl, wvh, wvl, Vp, nullptr, nullptr, 0, 0, 0);

    // S partials (fp32, deterministic split-K over sequence)
    s_partial_kernel<<<dim3(NBATCH * NHEAD, SPLITS), blk>>>();

    // U (fp32 compute, bf16 hi/lo planes out)
    u_kernel<<<dim3(NBATCH * NHEAD, HIDD / 256, 2), blk>>>(Wq);

    // Ct_b[n,k] = sum_j Wo[n,j] U_b[k,j]   (A = Wo shared, B = U_b)
    gemm3<true><<<dim3(HIDD / 128, HIDD / 128, NBATCH), blk, DSM_SIZE>>>(
        woh, wol, Uh, Ul, nullptr, Cth, Ctl, 0, HH, HH);

    // out_b[m,n] = sum_k h_b[m,k] Ct_b[n,k]
    gemm3<false><<<dim3(HIDD / 128, MSEQ / 128, NBATCH), blk, DSM_SIZE>>>(
        hh, hl, Cth, Ctl, out, nullptr, nullptr, MH, HH, MH);
}